// round 9
// baseline (speedup 1.0000x reference)
#include <cuda_runtime.h>
#include <cuda_bf16.h>
#include <cstdint>
#include <math.h>

#define Bn 8
#define Cn 256
#define Ln 512
#define NPn 6
#define KMAXn 17
#define HIDn 1024
#define SUMK 72

typedef long long ll;
typedef __nv_bfloat16 bf16;

// ---------------- scratch (device globals) ----------------------------------
__device__ __align__(16) bf16 g_ag  [(size_t)Bn*NPn*Cn*Ln];
__device__ __align__(16) bf16 g_vv  [(size_t)Bn*NPn*Cn*Ln];
__device__ __align__(16) bf16 g_v   [(size_t)Bn*NPn*Cn*Ln];
__device__ __align__(16) bf16 g_dcn [(size_t)Bn*NPn*Cn*Ln];
__device__ __align__(16) bf16 g_prod[(size_t)Bn*NPn*Cn*Ln];
__device__ __align__(16) bf16 g_off [(size_t)Bn*Cn*Ln*SUMK];
__device__ __align__(16) bf16 g_ml  [(size_t)Bn*Cn*Ln*SUMK];
__device__ __align__(16) float g_y  [(size_t)Bn*Cn*Ln];
__device__ __align__(16) bf16 g_tn  [(size_t)Bn*Cn*Ln];
__device__ __align__(16) bf16 g_h   [(size_t)Bn*HIDn*Ln];
__device__ float g_bps[Cn];
__device__ __align__(16) bf16 g_wa  [NPn*Cn*Cn];
__device__ __align__(16) bf16 g_wvd [NPn*Cn*Cn];
__device__ __align__(16) bf16 g_wod [NPn*Cn*Cn];
__device__ __align__(16) bf16 g_wv  [NPn*Cn*Cn];
__device__ __align__(16) bf16 g_wp  [NPn*Cn*Cn];
__device__ __align__(16) bf16 g_woff[(size_t)NPn*KMAXn*Cn*Cn];
__device__ __align__(16) bf16 g_wm  [(size_t)NPn*KMAXn*Cn*Cn];
__device__ __align__(16) bf16 g_w1  [HIDn*Cn];
__device__ __align__(16) bf16 g_w2  [Cn*HIDn];
__device__ __align__(16) bf16 g_xb  [(size_t)Bn*Cn*Ln];

__device__ __forceinline__ float gelu_f(float v) {
    return 0.5f * v * (1.0f + erff(v * 0.7071067811865476f));
}

// ---------------- fused conversion --------------------------------------
struct CvtArgs {
    const float* src[10];
    bf16* dst[10];
    int cum[11];
};
__global__ void __launch_bounds__(256)
cvtall_k(CvtArgs a)
{
    int total = a.cum[10];
    for (int i = blockIdx.x * 256 + threadIdx.x; i < total; i += gridDim.x * 256) {
        int s = 0;
        #pragma unroll
        for (int j = 1; j < 10; j++) if (i >= a.cum[j]) s = j;
        int off = i - a.cum[s];
        a.dst[s][off] = __float2bfloat16(a.src[s][off]);
    }
}

__global__ void bpsum_k(const float* __restrict__ bp, float* __restrict__ out)
{
    int c = threadIdx.x;
    float s = 0.f;
    #pragma unroll
    for (int i = 0; i < NPn; i++) s += bp[i * Cn + c];
    out[c] = s;
}

// ---------------- asm wrappers ----------------------------------------------
__device__ __forceinline__ void cpa16u(uint32_t dst, const void* src) {
    asm volatile("cp.async.cg.shared.global [%0], [%1], 16;\n" :: "r"(dst), "l"(src));
}
__device__ __forceinline__ void ldsm4(uint32_t addr, uint32_t& r0, uint32_t& r1,
                                      uint32_t& r2, uint32_t& r3) {
    asm volatile("ldmatrix.sync.aligned.m8n8.x4.shared.b16 {%0,%1,%2,%3}, [%4];\n"
        : "=r"(r0), "=r"(r1), "=r"(r2), "=r"(r3) : "r"(addr));
}
__device__ __forceinline__ void ldsm4t(uint32_t addr, uint32_t& r0, uint32_t& r1,
                                       uint32_t& r2, uint32_t& r3) {
    asm volatile("ldmatrix.sync.aligned.m8n8.x4.trans.shared.b16 {%0,%1,%2,%3}, [%4];\n"
        : "=r"(r0), "=r"(r1), "=r"(r2), "=r"(r3) : "r"(addr));
}
__device__ __forceinline__ void mma16816(float& d0, float& d1, float& d2, float& d3,
                                         uint32_t a0, uint32_t a1, uint32_t a2, uint32_t a3,
                                         uint32_t b0, uint32_t b1) {
    asm volatile(
        "mma.sync.aligned.m16n8k16.row.col.f32.bf16.bf16.f32 "
        "{%0,%1,%2,%3},{%4,%5,%6,%7},{%8,%9},{%0,%1,%2,%3};\n"
        : "+f"(d0), "+f"(d1), "+f"(d2), "+f"(d3)
        : "r"(a0), "r"(a1), "r"(a2), "r"(a3), "r"(b0), "r"(b1));
}

// ---------------- GEMM core: CTA 128x128, 4 warps (2x2), warp tile 64x64 -----
// Y[o][l] = epi(sum_c W[o,c] X[c][l] + bias[o]).
// A smem [3][128][32]: chunk phys = c ^ ((m>>1)&3); B smem [3][32*128]: phys = nc ^ (k&7)
template<int EPI, bool STACK, typename OutT>
__device__ __forceinline__ void gemm_core(
    bf16 (*As)[128][32], bf16 (*Bs)[4096],
    const bf16* __restrict__ Wz, const float* __restrict__ bz,
    const bf16* __restrict__ Xz, OutT* __restrict__ Yz,
    int KDIM, int m0, int n0,
    const void* __restrict__ aux, const float* __restrict__ svec)
{
    const int tid = threadIdx.x, lane = tid & 31, wid = tid >> 5;
    const int wm = wid >> 1, wn = wid & 1;

    float acc[4][8][4];
    #pragma unroll
    for (int i = 0; i < 4; i++)
        #pragma unroll
        for (int j = 0; j < 8; j++)
            #pragma unroll
            for (int q = 0; q < 4; q++) acc[i][j][q] = 0.f;

    const uint32_t asBase = (uint32_t)__cvta_generic_to_shared(&As[0][0][0]);
    const uint32_t bBase  = (uint32_t)__cvta_generic_to_shared(&Bs[0][0]);

    // ---- hoisted load addressing (128 threads; 4 reps each of A and B) ----
    // A: rows m = (tid>>2) + 32*rep, chunk c = tid&3. Swizzle bits are rep-invariant.
    // B: k = (tid>>4) + 8*rep, chunk nc = tid&15. Swizzle bits rep-invariant.
    const int mA = tid >> 2, cA = tid & 3;
    const int kB = tid >> 4, nB = tid & 15;
    const ll aRowStride = STACK ? (ll)Cn : (ll)KDIM;
    const bf16* srcA0 = Wz + (ll)(m0 + mA) * aRowStride + cA * 8;
    const bf16* srcB0 = Xz + (ll)kB * Ln + n0 + nB * 8;
    const uint32_t dA0 = asBase + (uint32_t)(mA * 64 + (cA ^ ((mA >> 1) & 3)) * 16);
    const uint32_t dB0 = bBase + (uint32_t)((kB * 16 + (nB ^ (kB & 7))) * 16);
    const ll aRep = 32 * aRowStride;   // +32 rows
    const ll bRep = 8 * Ln;            // +8 k-rows
    int kctr = 0;

    auto loadStage = [&](int s) {
        const bf16* a = srcA0;
        uint32_t da = dA0 + (uint32_t)(s * 8192);
        #pragma unroll
        for (int rep = 0; rep < 4; rep++) {
            cpa16u(da, a);
            da += 2048; a += aRep;
        }
        const bf16* bb = srcB0;
        uint32_t db = dB0 + (uint32_t)(s * 8192);
        #pragma unroll
        for (int rep = 0; rep < 4; rep++) {
            cpa16u(db, bb);
            db += 2048; bb += bRep;
        }
        srcB0 += 32 * Ln;
        if (STACK) {
            kctr += 32;
            ll d = 32;
            if ((kctr & 255) == 0) d += (ll)Cn * Cn - 256;
            srcA0 += d;
        } else {
            srcA0 += 32;
        }
    };

    // ---- hoisted ldmatrix addressing ----
    uint32_t aAddr[4][2], bAddr[4];
    #pragma unroll
    for (int mt = 0; mt < 4; mt++)
        #pragma unroll
        for (int ks = 0; ks < 2; ks++) {
            int rowp = wm * 64 + mt * 16 + (lane & 15);
            int physA = ((ks * 2) + (lane >> 4)) ^ ((rowp >> 1) & 3);
            aAddr[mt][ks] = asBase + (uint32_t)(rowp * 64 + physA * 16);
        }
    #pragma unroll
    for (int pr = 0; pr < 4; pr++) {
        int phys = (wn * 8 + pr * 2 + (lane >> 4)) ^ (lane & 7);
        bAddr[pr] = bBase + (uint32_t)((lane & 15) * 256 + phys * 16);
    }

    const int nIt = KDIM >> 5;
    loadStage(0);
    asm volatile("cp.async.commit_group;\n");
    loadStage(1);
    asm volatile("cp.async.commit_group;\n");

    int ldSlot = 2, rdSlot = 0;
    for (int it = 0; it < nIt; it++) {
        if (it + 1 < nIt) asm volatile("cp.async.wait_group 1;\n");
        else              asm volatile("cp.async.wait_group 0;\n");
        __syncthreads();
        if (it + 2 < nIt) {
            loadStage(ldSlot);
            ldSlot = (ldSlot == 2) ? 0 : ldSlot + 1;
        }
        asm volatile("cp.async.commit_group;\n");

        const uint32_t so = (uint32_t)(rdSlot * 8192);
        #pragma unroll
        for (int ks = 0; ks < 2; ks++) {
            uint32_t fa[4][4];
            #pragma unroll
            for (int mt = 0; mt < 4; mt++) {
                uint32_t t0, t1, t2, t3;
                ldsm4(aAddr[mt][ks] + so, t0, t1, t2, t3);
                fa[mt][0] = t0; fa[mt][1] = t1; fa[mt][2] = t2; fa[mt][3] = t3;
            }
            uint32_t fb[4][4];
            #pragma unroll
            for (int pr = 0; pr < 4; pr++) {
                uint32_t t0, t1, t2, t3;
                ldsm4t(bAddr[pr] + (uint32_t)(ks * 4096) + so, t0, t1, t2, t3);
                fb[pr][0] = t0; fb[pr][1] = t1; fb[pr][2] = t2; fb[pr][3] = t3;
            }
            #pragma unroll
            for (int mt = 0; mt < 4; mt++)
                #pragma unroll
                for (int nt = 0; nt < 8; nt++) {
                    float c0 = acc[mt][nt][0], c1 = acc[mt][nt][1];
                    float c2 = acc[mt][nt][2], c3 = acc[mt][nt][3];
                    mma16816(c0, c1, c2, c3,
                             fa[mt][0], fa[mt][1], fa[mt][2], fa[mt][3],
                             fb[nt >> 1][(nt & 1) * 2], fb[nt >> 1][(nt & 1) * 2 + 1]);
                    acc[mt][nt][0] = c0; acc[mt][nt][1] = c1;
                    acc[mt][nt][2] = c2; acc[mt][nt][3] = c3;
                }
        }
        rdSlot = (rdSlot == 2) ? 0 : rdSlot + 1;
    }

    // epilogue
    const int row = lane >> 2, colp = (lane & 3) * 2;
    #pragma unroll
    for (int mt = 0; mt < 4; mt++) {
        #pragma unroll
        for (int h = 0; h < 2; h++) {
            int o = m0 + wm * 64 + mt * 16 + row + h * 8;
            float bb = bz[o];
            float sv = (EPI == 3) ? svec[o] : 0.f;
            #pragma unroll
            for (int nt = 0; nt < 8; nt++) {
                int l = n0 + wn * 64 + nt * 8 + colp;
                ll yi = (ll)o * Ln + l;
                float r0 = acc[mt][nt][h * 2 + 0] + bb;
                float r1 = acc[mt][nt][h * 2 + 1] + bb;
                if (EPI == 1) { r0 = gelu_f(r0); r1 = gelu_f(r1); }
                if (EPI == 2) {
                    __nv_bfloat162 av = *(const __nv_bfloat162*)(((const bf16*)aux) + yi);
                    r0 *= __bfloat162float(av.x); r1 *= __bfloat162float(av.y);
                }
                if (EPI == 3) {
                    float2 av = *(const float2*)(((const float*)aux) + yi);
                    r0 = av.x + sv * r0; r1 = av.y + sv * r1;
                }
                if (sizeof(OutT) == 2) {
                    __nv_bfloat162 pv;
                    pv.x = __float2bfloat16(r0); pv.y = __float2bfloat16(r1);
                    *(__nv_bfloat162*)((bf16*)Yz + yi) = pv;
                } else {
                    float2 fv; fv.x = r0; fv.y = r1;
                    *(float2*)((float*)Yz + yi) = fv;
                }
            }
        }
    }
}

// ---------------- generic GEMM kernel wrapper --------------------------------
template<int EPI, bool STACK, typename OutT>
__global__ void __launch_bounds__(128, 2)
gemm_t(const bf16* __restrict__ W, const float* __restrict__ bias,
       const bf16* __restrict__ X, OutT* __restrict__ Y,
       int KDIM, int zB,
       ll wStrideI, int bStrideI,
       ll xStrideB, ll xStrideI,
       ll yStrideB, ll yStrideI,
       const void* __restrict__ aux, ll aStrideB, ll aStrideI,
       const float* __restrict__ svec)
{
    __shared__ __align__(16) bf16 As[3][128][32];
    __shared__ __align__(16) bf16 Bs[3][4096];
    const int z = blockIdx.z;
    const int b = z % zB, br = z / zB;
    const bf16*  Wz = W + (ll)br * wStrideI;
    const float* bz = bias + (ll)br * bStrideI;
    const bf16*  Xz = X + (ll)b * xStrideB + (ll)br * xStrideI;
    OutT* Yz = Y + (ll)b * yStrideB + (ll)br * yStrideI;
    const void* auxp = nullptr;
    if (EPI == 2) auxp = ((const bf16*)aux) + (ll)b * aStrideB + (ll)br * aStrideI;
    if (EPI == 3) auxp = ((const float*)aux) + (ll)b * aStrideB + (ll)br * aStrideI;
    gemm_core<EPI, STACK, OutT>(As, Bs, Wz, bz, Xz, Yz, KDIM,
                                blockIdx.y * 128, blockIdx.x * 128, auxp, svec);
}

// ---------------- fused off+ml mega-GEMM ------------------------------------
__global__ void __launch_bounds__(128, 2)
offml_k(const bf16* __restrict__ woff, const bf16* __restrict__ wm,
        const float* __restrict__ boff, const float* __restrict__ bm,
        const bf16* __restrict__ ag, bf16* __restrict__ offp, bf16* __restrict__ mlp)
{
    __shared__ __align__(16) bf16 As[3][128][32];
    __shared__ __align__(16) bf16 Bs[3][4096];
    const int bnd[7]  = {0, 14, 32, 54, 80, 110, 144};
    const int preK[6] = {0, 7, 16, 27, 40, 55};
    int t = blockIdx.y;
    int b = blockIdx.z;
    int kind = (t >= 144) ? 1 : 0;
    int tt = t - kind * 144;
    int br = 0;
    #pragma unroll
    for (int j = 1; j < 6; j++) if (tt >= bnd[j]) br = j;
    int mloc = (tt - bnd[br]) * 128;
    int K = 7 + 2 * br;
    const bf16*  W  = (kind ? wm : woff) + (ll)br * KMAXn * Cn * Cn + (ll)mloc * Cn;
    const float* bz = (kind ? bm : boff) + br * KMAXn * Cn + mloc;
    const bf16*  Xz = ag + ((ll)b * NPn + br) * ((ll)Cn * Ln);
    bf16* Y = (kind ? mlp : offp) + (ll)preK[br] * ((ll)Bn * Cn * Ln)
              + (ll)b * Cn * K * Ln + (ll)mloc * Ln;
    gemm_core<0, false, bf16>(As, Bs, W, bz, Xz, Y, Cn, 0, blockIdx.x * 128,
                              nullptr, nullptr);
}

// ---------------- DCN (all branches, one launch) -----------------------------
template<int K>
__device__ __forceinline__ void dcn_body(
    const bf16* __restrict__ off_all, const bf16* __restrict__ ml_all,
    const bf16* __restrict__ v_all, bf16* __restrict__ dcn,
    int branch, ll regionBase)
{
    ll idx = (ll)blockIdx.x * 256 + threadIdx.x;
    int l = (int)(idx & (Ln - 1));
    int c = (int)((idx >> 9) & (Cn - 1));
    int b = (int)(idx >> 17);
    ll rowBase = regionBase + ((ll)b * Cn * K + (ll)c * K) * Ln + l;
    const bf16* op = off_all + rowBase;
    const bf16* mp = ml_all + rowBase;
    const bf16* vp = v_all + ((ll)b * NPn + branch) * ((ll)Cn * Ln) + (ll)c * Ln;

    float mlv[K];
    float mx = -3.4e38f;
    #pragma unroll
    for (int k = 0; k < K; k++) { mlv[k] = __bfloat162float(mp[(ll)k * Ln]); mx = fmaxf(mx, mlv[k]); }
    float s = 0.f;
    #pragma unroll
    for (int k = 0; k < K; k++) { mlv[k] = expf(mlv[k] - mx); s += mlv[k]; }
    float inv = 1.f / s;

    float acc = 0.f;
    #pragma unroll
    for (int k = 0; k < K; k++) {
        float p = (float)l + ((float)k - (float)(K - 1) * 0.5f) + __bfloat162float(op[(ll)k * Ln]);
        float p0 = floorf(p);
        float w = p - p0;
        int i0 = (int)p0;
        float ga = (i0 >= 0 && i0 < Ln) ? __bfloat162float(vp[i0]) : 0.f;
        float gb = (i0 + 1 >= 0 && i0 + 1 < Ln) ? __bfloat162float(vp[i0 + 1]) : 0.f;
        acc += mlv[k] * ((1.f - w) * ga + w * gb);
    }
    dcn[((ll)b * NPn + branch) * ((ll)Cn * Ln) + (ll)c * Ln + l] = __float2bfloat16(acc * inv);
}

__global__ void __launch_bounds__(256)
dcnall_k(const bf16* __restrict__ offp, const bf16* __restrict__ mlp,
         const bf16* __restrict__ vp, bf16* __restrict__ dcnp)
{
    const ll BCL = (ll)Bn * Cn * Ln;
    switch (blockIdx.y) {
        case 0: dcn_body<7 >(offp, mlp, vp, dcnp, 0, (ll)0 * BCL);  break;
        case 1: dcn_body<9 >(offp, mlp, vp, dcnp, 1, (ll)7 * BCL);  break;
        case 2: dcn_body<11>(offp, mlp, vp, dcnp, 2, (ll)16 * BCL); break;
        case 3: dcn_body<13>(offp, mlp, vp, dcnp, 3, (ll)27 * BCL); break;
        case 4: dcn_body<15>(offp, mlp, vp, dcnp, 4, (ll)40 * BCL); break;
        default: dcn_body<17>(offp, mlp, vp, dcnp, 5, (ll)55 * BCL); break;
    }
}

// ---------------- LayerNorm over C ------------------------------------------
__global__ void __launch_bounds__(256)
ln_k(const float* __restrict__ y, const float* __restrict__ g,
     const float* __restrict__ be, bf16* __restrict__ tn)
{
    int l = blockIdx.x * 256 + threadIdx.x;
    int b = blockIdx.y;
    const float* yp = y + (ll)b * Cn * Ln + l;
    float s = 0.f, s2 = 0.f;
    #pragma unroll 8
    for (int c = 0; c < Cn; c++) {
        float v = yp[(ll)c * Ln];
        s += v; s2 += v * v;
    }
    float mu = s * (1.0f / Cn);
    float var = s2 * (1.0f / Cn) - mu * mu;
    float rstd = rsqrtf(var + 1e-6f);
    bf16* tp = tn + (ll)b * Cn * Ln + l;
    #pragma unroll 8
    for (int c = 0; c < Cn; c++) {
        float v = yp[(ll)c * Ln];
        tp[(ll)c * Ln] = __float2bfloat16((v - mu) * rstd * g[c] + be[c]);
    }
}

// ----------------------------------------------------------------------------
extern "C" void kernel_launch(void* const* d_in, const int* in_sizes, int n_in,
                              void* d_out, int out_size)
{
    const float* x    = (const float*)d_in[0];
    const float* Wa   = (const float*)d_in[1];
    const float* ba   = (const float*)d_in[2];
    const float* Wvd  = (const float*)d_in[3];
    const float* bvd  = (const float*)d_in[4];
    const float* Woff = (const float*)d_in[5];
    const float* boff = (const float*)d_in[6];
    const float* Wm   = (const float*)d_in[7];
    const float* bm   = (const float*)d_in[8];
    const float* Wod  = (const float*)d_in[9];
    const float* bod  = (const float*)d_in[10];
    const float* Wv   = (const float*)d_in[11];
    const float* bv   = (const float*)d_in[12];
    const float* Wp   = (const float*)d_in[13];
    const float* bp   = (const float*)d_in[14];
    const float* ls   = (const float*)d_in[15];
    const float* g2   = (const float*)d_in[16];
    const float* lng  = (const float*)d_in[17];
    const float* lnb  = (const float*)d_in[18];
    const float* W1   = (const float*)d_in[19];
    const float* b1   = (const float*)d_in[20];
    const float* W2   = (const float*)d_in[21];
    const float* b2   = (const float*)d_in[22];
    float* out = (float*)d_out;

    bf16 *ag, *vvp, *vp, *dcnp, *prodp, *offp, *mlp, *tnp, *hp, *xb;
    bf16 *wa, *wvd, *wod, *wv, *wp, *woff, *wm, *w1, *w2;
    float *yp, *bps;
    cudaGetSymbolAddress((void**)&ag,    g_ag);
    cudaGetSymbolAddress((void**)&vvp,   g_vv);
    cudaGetSymbolAddress((void**)&vp,    g_v);
    cudaGetSymbolAddress((void**)&dcnp,  g_dcn);
    cudaGetSymbolAddress((void**)&prodp, g_prod);
    cudaGetSymbolAddress((void**)&offp,  g_off);
    cudaGetSymbolAddress((void**)&mlp,   g_ml);
    cudaGetSymbolAddress((void**)&yp,    g_y);
    cudaGetSymbolAddress((void**)&tnp,   g_tn);
    cudaGetSymbolAddress((void**)&hp,    g_h);
    cudaGetSymbolAddress((void**)&bps,   g_bps);
    cudaGetSymbolAddress((void**)&wa,    g_wa);
    cudaGetSymbolAddress((void**)&wvd,   g_wvd);
    cudaGetSymbolAddress((void**)&wod,   g_wod);
    cudaGetSymbolAddress((void**)&wv,    g_wv);
    cudaGetSymbolAddress((void**)&wp,    g_wp);
    cudaGetSymbolAddress((void**)&woff,  g_woff);
    cudaGetSymbolAddress((void**)&wm,    g_wm);
    cudaGetSymbolAddress((void**)&w1,    g_w1);
    cudaGetSymbolAddress((void**)&w2,    g_w2);
    cudaGetSymbolAddress((void**)&xb,    g_xb);

    // fused conversions (single launch)
    CvtArgs ca;
    const float* srcs[10] = {x, Wa, Wvd, Wod, Wv, Wp, Woff, Wm, W1, W2};
    bf16* dsts[10] = {xb, wa, wvd, wod, wv, wp, woff, wm, w1, w2};
    int cnts[10] = {Bn*Cn*Ln, NPn*Cn*Cn, NPn*Cn*Cn, NPn*Cn*Cn, NPn*Cn*Cn, NPn*Cn*Cn,
                    NPn*KMAXn*Cn*Cn, NPn*KMAXn*Cn*Cn, HIDn*Cn, Cn*HIDn};
    ca.cum[0] = 0;
    for (int i = 0; i < 10; i++) {
        ca.src[i] = srcs[i]; ca.dst[i] = dsts[i];
        ca.cum[i + 1] = ca.cum[i] + cnts[i];
    }
    cvtall_k<<<8192, 256>>>(ca);
    bpsum_k<<<1, 256>>>(bp, bps);

    const ll SB = (ll)NPn * Cn * Ln;
    const ll SI = (ll)Cn * Ln;

    // G1: ag = gelu(Wa@x + ba)
    gemm_t<1, false, bf16><<<dim3(4, (NPn * Cn) / 128, Bn), 128>>>(
        wa, ba, xb, ag, Cn, Bn, 0, 0, SI, 0, SB, 0, nullptr, 0, 0, nullptr);
    // G2: vv = Wv@x + bv
    gemm_t<0, false, bf16><<<dim3(4, (NPn * Cn) / 128, Bn), 128>>>(
        wv, bv, xb, vvp, Cn, Bn, 0, 0, SI, 0, SB, 0, nullptr, 0, 0, nullptr);
    // G3: v = Wvd[i]@ag_i + bvd[i]
    gemm_t<0, false, bf16><<<dim3(4, Cn / 128, NPn * Bn), 128>>>(
        wvd, bvd, ag, vp, Cn, Bn, (ll)Cn * Cn, Cn, SB, SI, SB, SI,
        nullptr, 0, 0, nullptr);
    // G4+G5 fused: all off/ml projections in ONE launch
    offml_k<<<dim3(4, 288, Bn), 128>>>(woff, wm, boff, bm, ag, offp, mlp);
    // G6: DCN sampling (one launch, 6 branches)
    dcnall_k<<<dim3((Bn * Cn * Ln) / 256, NPn), 256>>>(offp, mlp, vp, dcnp);
    // G7: prod = (Wod[i]@dcn_i + bod[i]) * vv_i
    gemm_t<2, false, bf16><<<dim3(4, Cn / 128, NPn * Bn), 128>>>(
        wod, bod, dcnp, prodp, Cn, Bn, (ll)Cn * Cn, Cn, SB, SI, SB, SI,
        vvp, SB, SI, nullptr);
    // G8: y = x + ls * (sum_i Wp[i]@prod_i + bps)
    gemm_t<3, true, float><<<dim3(4, Cn / 128, Bn), 128>>>(
        wp, bps, prodp, yp, NPn * Cn, Bn, 0, 0, SB, 0, SI, 0,
        x, SI, 0, ls);
    // G9: LayerNorm
    ln_k<<<dim3(Ln / 256, Bn), 256>>>(yp, lng, lnb, tnp);
    // G10: h = gelu(W1@tn + b1)
    gemm_t<1, false, bf16><<<dim3(4, HIDn / 128, Bn), 128>>>(
        w1, b1, tnp, hp, Cn, Bn, 0, 0, SI, 0, (ll)HIDn * Ln, 0,
        nullptr, 0, 0, nullptr);
    // G11: out = y + g2 * (W2@h + b2)
    gemm_t<3, false, float><<<dim3(4, Cn / 128, Bn), 128>>>(
        w2, b2, hp, out, HIDn, Bn, 0, 0, (ll)HIDn * Ln, 0, SI, 0,
        yp, SI, 0, g2);
}

// round 10
// speedup vs baseline: 1.5238x; 1.5238x over previous
#include <cuda_runtime.h>
#include <cuda_fp16.h>
#include <cstdint>
#include <math.h>

#define Bn 8
#define Cn 256
#define Ln 512
#define NPn 6
#define KMAXn 17
#define HIDn 1024
#define SUMK 72

typedef long long ll;
typedef __half hf;

// ---------------- scratch (device globals) ----------------------------------
__device__ __align__(16) hf g_ag  [(size_t)Bn*NPn*Cn*Ln];
__device__ __align__(16) hf g_vv  [(size_t)Bn*NPn*Cn*Ln];
__device__ __align__(16) hf g_v   [(size_t)Bn*NPn*Cn*Ln];
__device__ __align__(16) hf g_dcn [(size_t)Bn*NPn*Cn*Ln];
__device__ __align__(16) hf g_prod[(size_t)Bn*NPn*Cn*Ln];
__device__ __align__(16) hf g_off [(size_t)Bn*Cn*Ln*SUMK];
__device__ __align__(16) hf g_ml  [(size_t)Bn*Cn*Ln*SUMK];
__device__ __align__(16) float g_y [(size_t)Bn*Cn*Ln];
__device__ __align__(16) hf g_tn  [(size_t)Bn*Cn*Ln];
__device__ __align__(16) hf g_h   [(size_t)Bn*HIDn*Ln];
__device__ float g_bps[Cn];
__device__ __align__(16) hf g_wa  [NPn*Cn*Cn];
__device__ __align__(16) hf g_wvd [NPn*Cn*Cn];
__device__ __align__(16) hf g_wod [NPn*Cn*Cn];
__device__ __align__(16) hf g_wv  [NPn*Cn*Cn];
__device__ __align__(16) hf g_wp  [NPn*Cn*Cn];
__device__ __align__(16) hf g_woff[(size_t)NPn*KMAXn*Cn*Cn];
__device__ __align__(16) hf g_wm  [(size_t)NPn*KMAXn*Cn*Cn];
__device__ __align__(16) hf g_w1  [HIDn*Cn];
__device__ __align__(16) hf g_w2  [Cn*HIDn];
__device__ __align__(16) hf g_xb  [(size_t)Bn*Cn*Ln];

__device__ __forceinline__ float gelu_f(float v) {
    return 0.5f * v * (1.0f + erff(v * 0.7071067811865476f));
}

// ---------------- fused conversion --------------------------------------
struct CvtArgs {
    const float* src[10];
    hf* dst[10];
    int cum[11];
};
__global__ void __launch_bounds__(256)
cvtall_k(CvtArgs a)
{
    int total = a.cum[10];
    for (int i = blockIdx.x * 256 + threadIdx.x; i < total; i += gridDim.x * 256) {
        int s = 0;
        #pragma unroll
        for (int j = 1; j < 10; j++) if (i >= a.cum[j]) s = j;
        int off = i - a.cum[s];
        a.dst[s][off] = __float2half(a.src[s][off]);
    }
}

__global__ void bpsum_k(const float* __restrict__ bp, float* __restrict__ out)
{
    int c = threadIdx.x;
    float s = 0.f;
    #pragma unroll
    for (int i = 0; i < NPn; i++) s += bp[i * Cn + c];
    out[c] = s;
}

// ---------------- asm wrappers ----------------------------------------------
__device__ __forceinline__ void cpa16u(uint32_t dst, const void* src) {
    asm volatile("cp.async.cg.shared.global [%0], [%1], 16;\n" :: "r"(dst), "l"(src));
}
__device__ __forceinline__ void ldsm4(uint32_t addr, uint32_t& r0, uint32_t& r1,
                                      uint32_t& r2, uint32_t& r3) {
    asm volatile("ldmatrix.sync.aligned.m8n8.x4.shared.b16 {%0,%1,%2,%3}, [%4];\n"
        : "=r"(r0), "=r"(r1), "=r"(r2), "=r"(r3) : "r"(addr));
}
__device__ __forceinline__ void ldsm4t(uint32_t addr, uint32_t& r0, uint32_t& r1,
                                       uint32_t& r2, uint32_t& r3) {
    asm volatile("ldmatrix.sync.aligned.m8n8.x4.trans.shared.b16 {%0,%1,%2,%3}, [%4];\n"
        : "=r"(r0), "=r"(r1), "=r"(r2), "=r"(r3) : "r"(addr));
}
// fp16 inputs, fp32 accum
__device__ __forceinline__ void mma_h32(float& d0, float& d1, float& d2, float& d3,
                                        uint32_t a0, uint32_t a1, uint32_t a2, uint32_t a3,
                                        uint32_t b0, uint32_t b1) {
    asm volatile(
        "mma.sync.aligned.m16n8k16.row.col.f32.f16.f16.f32 "
        "{%0,%1,%2,%3},{%4,%5,%6,%7},{%8,%9},{%0,%1,%2,%3};\n"
        : "+f"(d0), "+f"(d1), "+f"(d2), "+f"(d3)
        : "r"(a0), "r"(a1), "r"(a2), "r"(a3), "r"(b0), "r"(b1));
}
// fp16 inputs, fp16 accum (potential 2x rate)
__device__ __forceinline__ void mma_h16(uint32_t& d0, uint32_t& d1,
                                        uint32_t a0, uint32_t a1, uint32_t a2, uint32_t a3,
                                        uint32_t b0, uint32_t b1) {
    asm volatile(
        "mma.sync.aligned.m16n8k16.row.col.f16.f16.f16.f16 "
        "{%0,%1},{%2,%3,%4,%5},{%6,%7},{%0,%1};\n"
        : "+r"(d0), "+r"(d1)
        : "r"(a0), "r"(a1), "r"(a2), "r"(a3), "r"(b0), "r"(b1));
}

// ---------------- GEMM core (R7 config: 128x128 CTA, 8 warps 2x4... 2x2 of 32x64)
// A smem [3][128][32]: chunk phys = c ^ ((m>>1)&3); B smem [3][32*128]: phys = nc ^ (k&7)
template<int EPI, bool STACK, bool ACC16, typename OutT>
__device__ __forceinline__ void gemm_core(
    hf (*As)[128][32], hf (*Bs)[4096],
    const hf* __restrict__ Wz, const float* __restrict__ bz,
    const hf* __restrict__ Xz, OutT* __restrict__ Yz,
    int KDIM, int m0, int n0,
    const void* __restrict__ aux, const float* __restrict__ svec)
{
    const int tid = threadIdx.x, lane = tid & 31, wid = tid >> 5;
    const int wm = wid >> 1, wn = wid & 1;

    float acc[ACC16 ? 1 : 2][8][4];
    uint32_t acch[ACC16 ? 2 : 1][8][2];
    if (!ACC16) {
        #pragma unroll
        for (int i = 0; i < (ACC16 ? 1 : 2); i++)
            #pragma unroll
            for (int j = 0; j < 8; j++)
                #pragma unroll
                for (int q = 0; q < 4; q++) acc[i][j][q] = 0.f;
    } else {
        #pragma unroll
        for (int i = 0; i < (ACC16 ? 2 : 1); i++)
            #pragma unroll
            for (int j = 0; j < 8; j++) { acch[i][j][0] = 0u; acch[i][j][1] = 0u; }
    }

    const uint32_t asBase = (uint32_t)__cvta_generic_to_shared(&As[0][0][0]);
    const uint32_t bBase  = (uint32_t)__cvta_generic_to_shared(&Bs[0][0]);

    // ---- hoisted load addressing ----
    const int mA = tid >> 2, cA = tid & 3;
    const int kB = tid >> 4, nB = tid & 15;
    const hf *srcA0, *srcA1;
    if (STACK) {
        srcA0 = Wz + (ll)(m0 + mA) * Cn + cA * 8;
        srcA1 = Wz + (ll)(m0 + mA + 64) * Cn + cA * 8;
    } else {
        srcA0 = Wz + (ll)(m0 + mA) * KDIM + cA * 8;
        srcA1 = Wz + (ll)(m0 + mA + 64) * KDIM + cA * 8;
    }
    const hf* srcB0 = Xz + (ll)kB * Ln + n0 + nB * 8;
    const hf* srcB1 = Xz + (ll)(kB + 16) * Ln + n0 + nB * 8;
    const uint32_t dA0 = asBase + (uint32_t)(mA * 64 + (cA ^ ((mA >> 1) & 3)) * 16);
    const uint32_t dA1 = asBase + (uint32_t)((mA + 64) * 64 + (cA ^ (((mA + 64) >> 1) & 3)) * 16);
    const uint32_t dB0 = bBase + (uint32_t)((kB * 16 + (nB ^ (kB & 7))) * 16);
    const uint32_t dB1 = bBase + (uint32_t)(((kB + 16) * 16 + (nB ^ ((kB + 16) & 7))) * 16);
    int kctr = 0;

    auto loadStage = [&](uint32_t so) {
        cpa16u(dA0 + so, srcA0);
        cpa16u(dA1 + so, srcA1);
        cpa16u(dB0 + so, srcB0);
        cpa16u(dB1 + so, srcB1);
        srcB0 += 32 * Ln; srcB1 += 32 * Ln;
        if (STACK) {
            kctr += 32;
            ll d = 32;
            if ((kctr & 255) == 0) d += (ll)Cn * Cn - 256;
            srcA0 += d; srcA1 += d;
        } else {
            srcA0 += 32; srcA1 += 32;
        }
    };

    // ---- hoisted ldmatrix addressing ----
    uint32_t aAddr[2][2], bAddr[4];
    #pragma unroll
    for (int mt = 0; mt < 2; mt++)
        #pragma unroll
        for (int ks = 0; ks < 2; ks++) {
            int rowp = wm * 32 + mt * 16 + (lane & 15);
            int physA = ((ks * 2) + (lane >> 4)) ^ ((rowp >> 1) & 3);
            aAddr[mt][ks] = asBase + (uint32_t)(rowp * 64 + physA * 16);
        }
    #pragma unroll
    for (int pr = 0; pr < 4; pr++) {
        int phys = (wn * 8 + pr * 2 + (lane >> 4)) ^ (lane & 7);
        bAddr[pr] = bBase + (uint32_t)((lane & 15) * 256 + phys * 16);
    }

    const int nIt = KDIM >> 5;
    loadStage(0);
    asm volatile("cp.async.commit_group;\n");
    loadStage(8192);
    asm volatile("cp.async.commit_group;\n");

    uint32_t ldSlot = 16384, sOff = 0;
    for (int it = 0; it < nIt; it++) {
        if (it + 1 < nIt) asm volatile("cp.async.wait_group 1;\n");
        else              asm volatile("cp.async.wait_group 0;\n");
        __syncthreads();
        if (it + 2 < nIt) {
            loadStage(ldSlot);
            ldSlot = (ldSlot == 16384) ? 0 : ldSlot + 8192;
        }
        asm volatile("cp.async.commit_group;\n");

        #pragma unroll
        for (int ks = 0; ks < 2; ks++) {
            uint32_t fa[2][4];
            {
                uint32_t t0, t1, t2, t3;
                ldsm4(aAddr[0][ks] + sOff, t0, t1, t2, t3);
                fa[0][0] = t0; fa[0][1] = t1; fa[0][2] = t2; fa[0][3] = t3;
                ldsm4(aAddr[1][ks] + sOff, t0, t1, t2, t3);
                fa[1][0] = t0; fa[1][1] = t1; fa[1][2] = t2; fa[1][3] = t3;
            }
            uint32_t fb[4][4];
            #pragma unroll
            for (int pr = 0; pr < 4; pr++) {
                uint32_t t0, t1, t2, t3;
                ldsm4t(bAddr[pr] + (uint32_t)(ks * 4096) + sOff, t0, t1, t2, t3);
                fb[pr][0] = t0; fb[pr][1] = t1; fb[pr][2] = t2; fb[pr][3] = t3;
            }
            #pragma unroll
            for (int mt = 0; mt < 2; mt++)
                #pragma unroll
                for (int nt = 0; nt < 8; nt++) {
                    if (ACC16) {
                        uint32_t c0 = acch[mt][nt][0], c1 = acch[mt][nt][1];
                        mma_h16(c0, c1,
                                fa[mt][0], fa[mt][1], fa[mt][2], fa[mt][3],
                                fb[nt >> 1][(nt & 1) * 2], fb[nt >> 1][(nt & 1) * 2 + 1]);
                        acch[mt][nt][0] = c0; acch[mt][nt][1] = c1;
                    } else {
                        float c0 = acc[mt][nt][0], c1 = acc[mt][nt][1];
                        float c2 = acc[mt][nt][2], c3 = acc[mt][nt][3];
                        mma_h32(c0, c1, c2, c3,
                                fa[mt][0], fa[mt][1], fa[mt][2], fa[mt][3],
                                fb[nt >> 1][(nt & 1) * 2], fb[nt >> 1][(nt & 1) * 2 + 1]);
                        acc[mt][nt][0] = c0; acc[mt][nt][1] = c1;
                        acc[mt][nt][2] = c2; acc[mt][nt][3] = c3;
                    }
                }
        }
        sOff = (sOff == 16384) ? 0 : sOff + 8192;
    }

    // epilogue
    const int row = lane >> 2, colp = (lane & 3) * 2;
    #pragma unroll
    for (int mt = 0; mt < 2; mt++) {
        #pragma unroll
        for (int h = 0; h < 2; h++) {
            int o = m0 + wm * 32 + mt * 16 + row + h * 8;
            float bb = bz[o];
            float sv = (EPI == 3) ? svec[o] : 0.f;
            #pragma unroll
            for (int nt = 0; nt < 8; nt++) {
                int l = n0 + wn * 64 + nt * 8 + colp;
                ll yi = (ll)o * Ln + l;
                float r0, r1;
                if (ACC16) {
                    __half2 hv = *(__half2*)&acch[mt][nt][h];
                    r0 = __low2float(hv) + bb;
                    r1 = __high2float(hv) + bb;
                } else {
                    r0 = acc[mt][nt][h * 2 + 0] + bb;
                    r1 = acc[mt][nt][h * 2 + 1] + bb;
                }
                if (EPI == 1) { r0 = gelu_f(r0); r1 = gelu_f(r1); }
                if (EPI == 2) {
                    __half2 av = *(const __half2*)(((const hf*)aux) + yi);
                    r0 *= __low2float(av); r1 *= __high2float(av);
                }
                if (EPI == 3) {
                    float2 av = *(const float2*)(((const float*)aux) + yi);
                    r0 = av.x + sv * r0; r1 = av.y + sv * r1;
                }
                if (sizeof(OutT) == 2) {
                    __half2 pv = __floats2half2_rn(r0, r1);
                    *(__half2*)((hf*)Yz + yi) = pv;
                } else {
                    float2 fv; fv.x = r0; fv.y = r1;
                    *(float2*)((float*)Yz + yi) = fv;
                }
            }
        }
    }
}

// ---------------- generic GEMM kernel wrapper --------------------------------
template<int EPI, bool STACK, bool ACC16, typename OutT>
__global__ void __launch_bounds__(256, 2)
gemm_t(const hf* __restrict__ W, const float* __restrict__ bias,
       const hf* __restrict__ X, OutT* __restrict__ Y,
       int KDIM, int zB,
       ll wStrideI, int bStrideI,
       ll xStrideB, ll xStrideI,
       ll yStrideB, ll yStrideI,
       const void* __restrict__ aux, ll aStrideB, ll aStrideI,
       const float* __restrict__ svec)
{
    __shared__ __align__(16) hf As[3][128][32];
    __shared__ __align__(16) hf Bs[3][4096];
    const int z = blockIdx.z;
    const int b = z % zB, br = z / zB;
    const hf*  Wz = W + (ll)br * wStrideI;
    const float* bz = bias + (ll)br * bStrideI;
    const hf*  Xz = X + (ll)b * xStrideB + (ll)br * xStrideI;
    OutT* Yz = Y + (ll)b * yStrideB + (ll)br * yStrideI;
    const void* auxp = nullptr;
    if (EPI == 2) auxp = ((const hf*)aux) + (ll)b * aStrideB + (ll)br * aStrideI;
    if (EPI == 3) auxp = ((const float*)aux) + (ll)b * aStrideB + (ll)br * aStrideI;
    gemm_core<EPI, STACK, ACC16, OutT>(As, Bs, Wz, bz, Xz, Yz, KDIM,
                                       blockIdx.y * 128, blockIdx.x * 128, auxp, svec);
}

// ---------------- fused off+ml mega-GEMM ------------------------------------
__global__ void __launch_bounds__(256, 2)
offml_k(const hf* __restrict__ woff, const hf* __restrict__ wm,
        const float* __restrict__ boff, const float* __restrict__ bm,
        const hf* __restrict__ ag, hf* __restrict__ offp, hf* __restrict__ mlp)
{
    __shared__ __align__(16) hf As[3][128][32];
    __shared__ __align__(16) hf Bs[3][4096];
    const int bnd[7]  = {0, 14, 32, 54, 80, 110, 144};
    const int preK[6] = {0, 7, 16, 27, 40, 55};
    int t = blockIdx.y;
    int b = blockIdx.z;
    int kind = (t >= 144) ? 1 : 0;
    int tt = t - kind * 144;
    int br = 0;
    #pragma unroll
    for (int j = 1; j < 6; j++) if (tt >= bnd[j]) br = j;
    int mloc = (tt - bnd[br]) * 128;
    int K = 7 + 2 * br;
    const hf*    W  = (kind ? wm : woff) + (ll)br * KMAXn * Cn * Cn + (ll)mloc * Cn;
    const float* bz = (kind ? bm : boff) + br * KMAXn * Cn + mloc;
    const hf*    Xz = ag + ((ll)b * NPn + br) * ((ll)Cn * Ln);
    hf* Y = (kind ? mlp : offp) + (ll)preK[br] * ((ll)Bn * Cn * Ln)
            + (ll)b * Cn * K * Ln + (ll)mloc * Ln;
    gemm_core<0, false, true, hf>(As, Bs, W, bz, Xz, Y, Cn, 0, blockIdx.x * 128,
                                  nullptr, nullptr);
}

// ---------------- DCN (all branches, one launch) -----------------------------
template<int K>
__device__ __forceinline__ void dcn_body(
    const hf* __restrict__ off_all, const hf* __restrict__ ml_all,
    const hf* __restrict__ v_all, hf* __restrict__ dcn,
    int branch, ll regionBase)
{
    ll idx = (ll)blockIdx.x * 256 + threadIdx.x;
    int l = (int)(idx & (Ln - 1));
    int c = (int)((idx >> 9) & (Cn - 1));
    int b = (int)(idx >> 17);
    ll rowBase = regionBase + ((ll)b * Cn * K + (ll)c * K) * Ln + l;
    const hf* op = off_all + rowBase;
    const hf* mp = ml_all + rowBase;
    const hf* vp = v_all + ((ll)b * NPn + branch) * ((ll)Cn * Ln) + (ll)c * Ln;

    float mlv[K];
    float mx = -3.4e38f;
    #pragma unroll
    for (int k = 0; k < K; k++) { mlv[k] = __half2float(mp[(ll)k * Ln]); mx = fmaxf(mx, mlv[k]); }
    float s = 0.f;
    #pragma unroll
    for (int k = 0; k < K; k++) { mlv[k] = expf(mlv[k] - mx); s += mlv[k]; }
    float inv = 1.f / s;

    float acc = 0.f;
    #pragma unroll
    for (int k = 0; k < K; k++) {
        float p = (float)l + ((float)k - (float)(K - 1) * 0.5f) + __half2float(op[(ll)k * Ln]);
        float p0 = floorf(p);
        float w = p - p0;
        int i0 = (int)p0;
        float ga = (i0 >= 0 && i0 < Ln) ? __half2float(vp[i0]) : 0.f;
        float gb = (i0 + 1 >= 0 && i0 + 1 < Ln) ? __half2float(vp[i0 + 1]) : 0.f;
        acc += mlv[k] * ((1.f - w) * ga + w * gb);
    }
    dcn[((ll)b * NPn + branch) * ((ll)Cn * Ln) + (ll)c * Ln + l] = __float2half(acc * inv);
}

__global__ void __launch_bounds__(256)
dcnall_k(const hf* __restrict__ offp, const hf* __restrict__ mlp,
         const hf* __restrict__ vp, hf* __restrict__ dcnp)
{
    const ll BCL = (ll)Bn * Cn * Ln;
    switch (blockIdx.y) {
        case 0: dcn_body<7 >(offp, mlp, vp, dcnp, 0, (ll)0 * BCL);  break;
        case 1: dcn_body<9 >(offp, mlp, vp, dcnp, 1, (ll)7 * BCL);  break;
        case 2: dcn_body<11>(offp, mlp, vp, dcnp, 2, (ll)16 * BCL); break;
        case 3: dcn_body<13>(offp, mlp, vp, dcnp, 3, (ll)27 * BCL); break;
        case 4: dcn_body<15>(offp, mlp, vp, dcnp, 4, (ll)40 * BCL); break;
        default: dcn_body<17>(offp, mlp, vp, dcnp, 5, (ll)55 * BCL); break;
    }
}

// ---------------- LayerNorm over C ------------------------------------------
__global__ void __launch_bounds__(256)
ln_k(const float* __restrict__ y, const float* __restrict__ g,
     const float* __restrict__ be, hf* __restrict__ tn)
{
    int l = blockIdx.x * 256 + threadIdx.x;
    int b = blockIdx.y;
    const float* yp = y + (ll)b * Cn * Ln + l;
    float s = 0.f, s2 = 0.f;
    #pragma unroll 8
    for (int c = 0; c < Cn; c++) {
        float v = yp[(ll)c * Ln];
        s += v; s2 += v * v;
    }
    float mu = s * (1.0f / Cn);
    float var = s2 * (1.0f / Cn) - mu * mu;
    float rstd = rsqrtf(var + 1e-6f);
    hf* tp = tn + (ll)b * Cn * Ln + l;
    #pragma unroll 8
    for (int c = 0; c < Cn; c++) {
        float v = yp[(ll)c * Ln];
        tp[(ll)c * Ln] = __float2half((v - mu) * rstd * g[c] + be[c]);
    }
}

// ----------------------------------------------------------------------------
extern "C" void kernel_launch(void* const* d_in, const int* in_sizes, int n_in,
                              void* d_out, int out_size)
{
    const float* x    = (const float*)d_in[0];
    const float* Wa   = (const float*)d_in[1];
    const float* ba   = (const float*)d_in[2];
    const float* Wvd  = (const float*)d_in[3];
    const float* bvd  = (const float*)d_in[4];
    const float* Woff = (const float*)d_in[5];
    const float* boff = (const float*)d_in[6];
    const float* Wm   = (const float*)d_in[7];
    const float* bm   = (const float*)d_in[8];
    const float* Wod  = (const float*)d_in[9];
    const float* bod  = (const float*)d_in[10];
    const float* Wv   = (const float*)d_in[11];
    const float* bv   = (const float*)d_in[12];
    const float* Wp   = (const float*)d_in[13];
    const float* bp   = (const float*)d_in[14];
    const float* ls   = (const float*)d_in[15];
    const float* g2   = (const float*)d_in[16];
    const float* lng  = (const float*)d_in[17];
    const float* lnb  = (const float*)d_in[18];
    const float* W1   = (const float*)d_in[19];
    const float* b1   = (const float*)d_in[20];
    const float* W2   = (const float*)d_in[21];
    const float* b2   = (const float*)d_in[22];
    float* out = (float*)d_out;

    hf *ag, *vvp, *vp, *dcnp, *prodp, *offp, *mlp, *tnp, *hp, *xb;
    hf *wa, *wvd, *wod, *wv, *wp, *woff, *wm, *w1, *w2;
    float *yp, *bps;
    cudaGetSymbolAddress((void**)&ag,    g_ag);
    cudaGetSymbolAddress((void**)&vvp,   g_vv);
    cudaGetSymbolAddress((void**)&vp,    g_v);
    cudaGetSymbolAddress((void**)&dcnp,  g_dcn);
    cudaGetSymbolAddress((void**)&prodp, g_prod);
    cudaGetSymbolAddress((void**)&offp,  g_off);
    cudaGetSymbolAddress((void**)&mlp,   g_ml);
    cudaGetSymbolAddress((void**)&yp,    g_y);
    cudaGetSymbolAddress((void**)&tnp,   g_tn);
    cudaGetSymbolAddress((void**)&hp,    g_h);
    cudaGetSymbolAddress((void**)&bps,   g_bps);
    cudaGetSymbolAddress((void**)&wa,    g_wa);
    cudaGetSymbolAddress((void**)&wvd,   g_wvd);
    cudaGetSymbolAddress((void**)&wod,   g_wod);
    cudaGetSymbolAddress((void**)&wv,    g_wv);
    cudaGetSymbolAddress((void**)&wp,    g_wp);
    cudaGetSymbolAddress((void**)&woff,  g_woff);
    cudaGetSymbolAddress((void**)&wm,    g_wm);
    cudaGetSymbolAddress((void**)&w1,    g_w1);
    cudaGetSymbolAddress((void**)&w2,    g_w2);
    cudaGetSymbolAddress((void**)&xb,    g_xb);

    // fused conversions (single launch)
    CvtArgs ca;
    const float* srcs[10] = {x, Wa, Wvd, Wod, Wv, Wp, Woff, Wm, W1, W2};
    hf* dsts[10] = {xb, wa, wvd, wod, wv, wp, woff, wm, w1, w2};
    int cnts[10] = {Bn*Cn*Ln, NPn*Cn*Cn, NPn*Cn*Cn, NPn*Cn*Cn, NPn*Cn*Cn, NPn*Cn*Cn,
                    NPn*KMAXn*Cn*Cn, NPn*KMAXn*Cn*Cn, HIDn*Cn, Cn*HIDn};
    ca.cum[0] = 0;
    for (int i = 0; i < 10; i++) {
        ca.src[i] = srcs[i]; ca.dst[i] = dsts[i];
        ca.cum[i + 1] = ca.cum[i] + cnts[i];
    }
    cvtall_k<<<8192, 256>>>(ca);
    bpsum_k<<<1, 256>>>(bp, bps);

    const ll SB = (ll)NPn * Cn * Ln;
    const ll SI = (ll)Cn * Ln;

    // G1: ag = gelu(Wa@x + ba)                      (f16 accum)
    gemm_t<1, false, true, hf><<<dim3(4, (NPn * Cn) / 128, Bn), 256>>>(
        wa, ba, xb, ag, Cn, Bn, 0, 0, SI, 0, SB, 0, nullptr, 0, 0, nullptr);
    // G2: vv = Wv@x + bv                            (f16 accum)
    gemm_t<0, false, true, hf><<<dim3(4, (NPn * Cn) / 128, Bn), 256>>>(
        wv, bv, xb, vvp, Cn, Bn, 0, 0, SI, 0, SB, 0, nullptr, 0, 0, nullptr);
    // G3: v = Wvd[i]@ag_i + bvd[i]                  (f16 accum)
    gemm_t<0, false, true, hf><<<dim3(4, Cn / 128, NPn * Bn), 256>>>(
        wvd, bvd, ag, vp, Cn, Bn, (ll)Cn * Cn, Cn, SB, SI, SB, SI,
        nullptr, 0, 0, nullptr);
    // G4+G5 fused: all off/ml projections            (f16 accum)
    offml_k<<<dim3(4, 288, Bn), 256>>>(woff, wm, boff, bm, ag, offp, mlp);
    // G6: DCN sampling (one launch, 6 branches)
    dcnall_k<<<dim3((Bn * Cn * Ln) / 256, NPn), 256>>>(offp, mlp, vp, dcnp);
    // G7: prod = (Wod[i]@dcn_i + bod[i]) * vv_i      (f16 accum)
    gemm_t<2, false, true, hf><<<dim3(4, Cn / 128, NPn * Bn), 256>>>(
        wod, bod, dcnp, prodp, Cn, Bn, (ll)Cn * Cn, Cn, SB, SI, SB, SI,
        vvp, SB, SI, nullptr);
    // G8: y = x + ls * (sum_i Wp[i]@prod_i + bps)    (f32 accum)
    gemm_t<3, true, false, float><<<dim3(4, Cn / 128, Bn), 256>>>(
        wp, bps, prodp, yp, NPn * Cn, Bn, 0, 0, SB, 0, SI, 0,
        x, SI, 0, ls);
    // G9: LayerNorm
    ln_k<<<dim3(Ln / 256, Bn), 256>>>(yp, lng, lnb, tnp);
    // G10: h = gelu(W1@tn + b1)                      (f16 accum)
    gemm_t<1, false, true, hf><<<dim3(4, HIDn / 128, Bn), 256>>>(
        w1, b1, tnp, hp, Cn, Bn, 0, 0, SI, 0, (ll)HIDn * Ln, 0,
        nullptr, 0, 0, nullptr);
    // G11: out = y + g2 * (W2@h + b2)                (f32 accum)
    gemm_t<3, false, false, float><<<dim3(4, Cn / 128, Bn), 256>>>(
        w2, b2, hp, out, HIDn, Bn, 0, 0, (ll)HIDn * Ln, 0, SI, 0,
        yp, SI, 0, g2);
}